// round 9
// baseline (speedup 1.0000x reference)
#include <cuda_runtime.h>
#include <cuda_fp16.h>
#include <math.h>
#include <stdint.h>

#define HIDN 1024
#define MROWS 4096
#define SEQ 1024
#define NHEAD 16
#define HDIM 64
#define MSZ (MROWS * HIDN)
#define WSZ (HIDN * HIDN)

// GEMM tiling: 128x256 CTA, 8 warps (2x4), warp tile 64x64, 3-stage
#define BM 128
#define BN 256
#define BK 32
#define NS (HIDN / BK)
#define LDT 40                        // fp16 row stride (32 + 8 pad)
#define ATB (128 * LDT * 2)           // 10240
#define BTB (256 * LDT * 2)           // 20480
#define OFF_A 0
#define OFF_BHI ATB
#define OFF_BLO (ATB + BTB)
#define SSTRIDE (ATB + 2 * BTB)       // 51200
#define GEMM_SMEM (3 * SSTRIDE)       // 153600, 1 CTA/SM

// attention tiling (Q hi, K hi+lo, V hi; double-buffered)
#define ALD 72
#define ATILE_B (64 * ALD * 2)
#define SQH 0
#define SKH(st) (ATILE_B * (1 + (st) * 3))
#define SKL(st) (SKH(st) + ATILE_B)
#define SVH(st) (SKH(st) + 2 * ATILE_B)
#define SMSK(st) (7 * ATILE_B + (st) * 256)
#define ATTN_SMEM (7 * ATILE_B + 512)  // 65024 => 3 CTAs/SM

// ---------------- scratch (device globals; no allocation allowed) ----------
// hi/lo slots: 0..2 = LN(q,k,v); 3 = Fx; 4 = Q(rope); 5 = K(rope); 6 = V
__device__ __align__(16) __half g_hi[7L * MSZ];
__device__ __align__(16) __half g_lo[7L * MSZ];
__device__ __align__(16) __half g_Whi[4L * WSZ];
__device__ __align__(16) __half g_Wlo[4L * WSZ];
__device__ __align__(16) float g_X [MSZ];
__device__ __align__(16) float g_Fx[MSZ];
__device__ __align__(16) float g_Fo[MSZ];
__device__ __align__(16) float2 g_rope[SEQ * 32];   // (cos, sin) per (pos, i)

// ---------------- PTX helpers ----------------
__device__ __forceinline__ void cp16(uint32_t dst, const void* src) {
  asm volatile("cp.async.cg.shared.global [%0], [%1], 16;\n"
               :: "r"(dst), "l"(__cvta_generic_to_global(src)) : "memory");
}
#define CP_COMMIT() asm volatile("cp.async.commit_group;" ::: "memory")
#define CP_WAIT1()  asm volatile("cp.async.wait_group 1;" ::: "memory")
#define CP_WAIT0()  asm volatile("cp.async.wait_group 0;" ::: "memory")

#define LDSM4(r, addr) asm volatile( \
  "ldmatrix.sync.aligned.m8n8.x4.shared.b16 {%0,%1,%2,%3}, [%4];" \
  : "=r"((r)[0]), "=r"((r)[1]), "=r"((r)[2]), "=r"((r)[3]) : "r"(addr))

#define LDSM4T(r, addr) asm volatile( \
  "ldmatrix.sync.aligned.m8n8.x4.trans.shared.b16 {%0,%1,%2,%3}, [%4];" \
  : "=r"((r)[0]), "=r"((r)[1]), "=r"((r)[2]), "=r"((r)[3]) : "r"(addr))

#define MMA(acc, a, b0, b1) asm volatile( \
  "mma.sync.aligned.m16n8k16.row.col.f32.f16.f16.f32 " \
  "{%0,%1,%2,%3}, {%4,%5,%6,%7}, {%8,%9}, {%0,%1,%2,%3};" \
  : "+f"((acc)[0]), "+f"((acc)[1]), "+f"((acc)[2]), "+f"((acc)[3]) \
  : "r"((a)[0]), "r"((a)[1]), "r"((a)[2]), "r"((a)[3]), "r"(b0), "r"(b1))

__device__ __forceinline__ uint32_t pack_h2(float a, float b) {
  __half2 h(__float2half_rn(a), __float2half_rn(b));
  return *(uint32_t*)&h;
}
__device__ __forceinline__ void split2h(float a, float b, uint32_t& hi, uint32_t& lo) {
  __half ha = __float2half_rn(a), hb = __float2half_rn(b);
  __half2 h(ha, hb);
  __half2 l(__float2half_rn(a - __half2float(ha)),
            __float2half_rn(b - __half2float(hb)));
  hi = *(uint32_t*)&h;
  lo = *(uint32_t*)&l;
}

// ---------------- reductions ----------------
__device__ __forceinline__ float warpSum(float v) {
#pragma unroll
  for (int o = 16; o; o >>= 1) v += __shfl_xor_sync(0xffffffffu, v, o);
  return v;
}
__device__ __forceinline__ float blockSum(float partial, float* sh) {
  __syncthreads();
  float w = warpSum(partial);
  if ((threadIdx.x & 31) == 0) sh[threadIdx.x >> 5] = w;
  __syncthreads();
  float tot = 0.f;
#pragma unroll
  for (int i = 0; i < 8; i++) tot += sh[i];
  return tot;
}

// ---------------- rope table ----------------
__global__ __launch_bounds__(512)
void rope_table_kernel() {
  const int idx = blockIdx.x * 512 + threadIdx.x;  // s*32 + i
  const int s = idx >> 5, i = idx & 31;
  float inv = exp2f(-(float)i * (13.287712379549449f / 32.f));
  float sn, cs;
  sincosf((float)s * inv, &sn, &cs);
  g_rope[idx] = make_float2(cs, sn);
}

// ---------------- weight split: fp32 -> fp16 hi/lo -------------------------
__global__ __launch_bounds__(256)
void wconv_kernel(const float* __restrict__ w0, const float* __restrict__ w1,
                  const float* __restrict__ w2, const float* __restrict__ w3) {
  const float* src = blockIdx.y == 0 ? w0 : blockIdx.y == 1 ? w1
                   : blockIdx.y == 2 ? w2 : w3;
  const long base = (long)blockIdx.y * WSZ;
  const long i = ((long)blockIdx.x * 256 + threadIdx.x) * 4;
  float4 v = *(const float4*)(src + i);
  uint32_t h0, l0, h1, l1;
  split2h(v.x, v.y, h0, l0);
  split2h(v.z, v.w, h1, l1);
  *(uint32_t*)(g_Whi + base + i)     = h0;
  *(uint32_t*)(g_Whi + base + i + 2) = h1;
  *(uint32_t*)(g_Wlo + base + i)     = l0;
  *(uint32_t*)(g_Wlo + base + i + 2) = l1;
}

// ---------------- LayerNorm x3 -> fp16 hi slots 0..2 -----------------------
__global__ __launch_bounds__(256)
void ln3_kernel(const float* __restrict__ x0, const float* __restrict__ g0,
                const float* __restrict__ b0, const float* __restrict__ x1,
                const float* __restrict__ g1, const float* __restrict__ b1,
                const float* __restrict__ x2, const float* __restrict__ g2,
                const float* __restrict__ b2) {
  __shared__ float sh[8];
  const int y = blockIdx.y;
  const float* x = y == 0 ? x0 : y == 1 ? x1 : x2;
  const float* g = y == 0 ? g0 : y == 1 ? g1 : g2;
  const float* b = y == 0 ? b0 : y == 1 ? b1 : b2;
  const int row = blockIdx.x, t = threadIdx.x;
  float4 v = ((const float4*)(x + (long)row * HIDN))[t];
  float mean = blockSum(v.x + v.y + v.z + v.w, sh) * (1.f / HIDN);
  float dx = v.x - mean, dy = v.y - mean, dz = v.z - mean, dw = v.w - mean;
  float var = blockSum(dx * dx + dy * dy + dz * dz + dw * dw, sh) * (1.f / HIDN);
  float rstd = rsqrtf(var + 1e-5f);
  float4 gv = ((const float4*)g)[t];
  float4 bv = ((const float4*)b)[t];
  const long off = (long)y * MSZ + (long)row * HIDN + t * 4;
  *(uint32_t*)(g_hi + off) =
      pack_h2(dx * rstd * gv.x + bv.x, dy * rstd * gv.y + bv.y);
  *(uint32_t*)(g_hi + off + 2) =
      pack_h2(dz * rstd * gv.z + bv.z, dw * rstd * gv.w + bv.w);
}

// fx = LN(g_X) -> g_Fx fp32 + slot3 fp16 hi
__global__ __launch_bounds__(256)
void ln_fx_kernel(const float* __restrict__ g, const float* __restrict__ b) {
  __shared__ float sh[8];
  const int row = blockIdx.x, t = threadIdx.x;
  float4 v = ((const float4*)(g_X + (long)row * HIDN))[t];
  float mean = blockSum(v.x + v.y + v.z + v.w, sh) * (1.f / HIDN);
  float dx = v.x - mean, dy = v.y - mean, dz = v.z - mean, dw = v.w - mean;
  float var = blockSum(dx * dx + dy * dy + dz * dz + dw * dw, sh) * (1.f / HIDN);
  float rstd = rsqrtf(var + 1e-5f);
  float4 gv = ((const float4*)g)[t];
  float4 bv = ((const float4*)b)[t];
  float4 o = make_float4(dx * rstd * gv.x + bv.x, dy * rstd * gv.y + bv.y,
                         dz * rstd * gv.z + bv.z, dw * rstd * gv.w + bv.w);
  ((float4*)(g_Fx + (long)row * HIDN))[t] = o;
  const long off = 3L * MSZ + (long)row * HIDN + t * 4;
  *(uint32_t*)(g_hi + off)     = pack_h2(o.x, o.y);
  *(uint32_t*)(g_hi + off + 2) = pack_h2(o.z, o.w);
}

// out = g_Fx + LN(g_Fo)*g3 + b3
__global__ __launch_bounds__(256)
void ln_add_kernel(const float* __restrict__ g, const float* __restrict__ b,
                   float* __restrict__ out) {
  __shared__ float sh[8];
  const int row = blockIdx.x, t = threadIdx.x;
  float4 v = ((const float4*)(g_Fo + (long)row * HIDN))[t];
  float mean = blockSum(v.x + v.y + v.z + v.w, sh) * (1.f / HIDN);
  float dx = v.x - mean, dy = v.y - mean, dz = v.z - mean, dw = v.w - mean;
  float var = blockSum(dx * dx + dy * dy + dz * dz + dw * dw, sh) * (1.f / HIDN);
  float rstd = rsqrtf(var + 1e-5f);
  float4 gv = ((const float4*)g)[t];
  float4 bv = ((const float4*)b)[t];
  float4 fx = ((const float4*)(g_Fx + (long)row * HIDN))[t];
  float4 o = make_float4(fx.x + dx * rstd * gv.x + bv.x,
                         fx.y + dy * rstd * gv.y + bv.y,
                         fx.z + dz * rstd * gv.z + bv.z,
                         fx.w + dw * rstd * gv.w + bv.w);
  ((float4*)(out + (long)row * HIDN))[t] = o;
}

// ---------------- fp16 2-term GEMM with fused epilogue ---------------------
// mode: 0=Q (rope, hi), 1=K (rope, hi+lo), 2=V (hi), 3=FFN (relu, fp32)
__device__ __forceinline__ void gemm_load_stage(
    uint32_t sbase, const __half* Ah, const __half* Bh, const __half* Bl,
    int row0, int col0, int k0, int t) {
#pragma unroll
  for (int j = 0; j < 2; j++) {
    const int idx = t + j * 256;
    const int r = idx >> 2, cc = idx & 3;
    cp16(sbase + (uint32_t)(r * (LDT * 2) + cc * 16) + OFF_A,
         Ah + (long)(row0 + r) * HIDN + k0 + cc * 8);
  }
#pragma unroll
  for (int j = 0; j < 4; j++) {
    const int idx = t + j * 256;
    const int r = idx >> 2, cc = idx & 3;
    const uint32_t so = sbase + (uint32_t)(r * (LDT * 2) + cc * 16);
    const long gb = (long)(col0 + r) * HIDN + k0 + cc * 8;
    cp16(so + OFF_BHI, Bh + gb);
    cp16(so + OFF_BLO, Bl + gb);
  }
}

__global__ __launch_bounds__(256, 1)
void gemm_mma(int ffn, const float* __restrict__ bias0,
              const float* __restrict__ bias1, const float* __restrict__ bias2) {
  extern __shared__ __align__(128) char smem[];
  const int z = blockIdx.z;
  const int mode = ffn ? 3 : z;
  const int slot = ffn ? 3 : z;
  const __half* Ah = g_hi  + (long)slot * MSZ;
  const __half* Bh = g_Whi + (long)slot * WSZ;
  const __half* Bl = g_Wlo + (long)slot * WSZ;
  const float* bias = (z == 0) ? bias0 : ((z == 1) ? bias1 : bias2);

  const int t = threadIdx.x;
  const int wid = t >> 5, lane = t & 31;
  const int wm = wid >> 2, wn = wid & 3;
  const int row0 = blockIdx.y * BM, col0 = blockIdx.x * BN;
  const uint32_t sb = (uint32_t)__cvta_generic_to_shared(smem);

  float acc[4][8][4];
#pragma unroll
  for (int i = 0; i < 4; i++)
#pragma unroll
    for (int j = 0; j < 8; j++)
#pragma unroll
      for (int r = 0; r < 4; r++) acc[i][j][r] = 0.f;

  gemm_load_stage(sb,           Ah, Bh, Bl, row0, col0, 0,  t);
  CP_COMMIT();
  gemm_load_stage(sb + SSTRIDE, Ah, Bh, Bl, row0, col0, BK, t);
  CP_COMMIT();

  const uint32_t aOff = (uint32_t)((wm * 64 + (lane & 15)) * (LDT * 2) + (lane >> 4) * 16);
  const uint32_t bOff = (uint32_t)((wn * 64 + (lane & 15)) * (LDT * 2) + (lane >> 4) * 16);

  for (int s = 0; s < NS; s++) {
    CP_WAIT1();
    __syncthreads();
    const uint32_t st = sb + (uint32_t)((s % 3) * SSTRIDE);
#pragma unroll
    for (int kk = 0; kk < 2; kk++) {
      uint32_t ah[4][4];
#pragma unroll
      for (int mi = 0; mi < 4; mi++) {
        LDSM4(ah[mi], st + aOff + (uint32_t)(mi * 16 * (LDT * 2) + kk * 32) + OFF_A);
      }
#pragma unroll
      for (int bn = 0; bn < 4; bn++) {
        uint32_t bh4[4], bl4[4];
        const uint32_t a = st + bOff + (uint32_t)(bn * 16 * (LDT * 2) + kk * 32);
        LDSM4(bh4, a + OFF_BHI);
        LDSM4(bl4, a + OFF_BLO);
#pragma unroll
        for (int mi = 0; mi < 4; mi++) {
          MMA(acc[mi][2 * bn],     ah[mi], bh4[0], bh4[2]);
          MMA(acc[mi][2 * bn],     ah[mi], bl4[0], bl4[2]);
          MMA(acc[mi][2 * bn + 1], ah[mi], bh4[1], bh4[3]);
          MMA(acc[mi][2 * bn + 1], ah[mi], bl4[1], bl4[3]);
        }
      }
    }
    __syncthreads();
    if (s + 2 < NS) {
      gemm_load_stage(sb + (uint32_t)(((s + 2) % 3) * SSTRIDE),
                      Ah, Bh, Bl, row0, col0, (s + 2) * BK, t);
    }
    CP_COMMIT();
  }

  // ---------------- fused epilogue ----------------
  if (mode == 3) {            // FFN: relu -> g_Fo fp32
#pragma unroll
    for (int mi = 0; mi < 4; mi++) {
      const long r = row0 + wm * 64 + mi * 16 + (lane >> 2);
#pragma unroll
      for (int ni = 0; ni < 8; ni++) {
        const int c = col0 + wn * 64 + ni * 8 + (lane & 3) * 2;
        float2 bv = *(const float2*)(bias + c);
        *(float2*)(g_Fo + r * HIDN + c) =
            make_float2(fmaxf(acc[mi][ni][0] + bv.x, 0.f),
                        fmaxf(acc[mi][ni][1] + bv.y, 0.f));
        *(float2*)(g_Fo + (r + 8) * HIDN + c) =
            make_float2(fmaxf(acc[mi][ni][2] + bv.x, 0.f),
                        fmaxf(acc[mi][ni][3] + bv.y, 0.f));
      }
    }
  } else if (mode == 2) {     // V: hi fp16
    __half* dh = g_hi + 6L * MSZ;
#pragma unroll
    for (int mi = 0; mi < 4; mi++) {
      const long r = row0 + wm * 64 + mi * 16 + (lane >> 2);
#pragma unroll
      for (int ni = 0; ni < 8; ni++) {
        const int c = col0 + wn * 64 + ni * 8 + (lane & 3) * 2;
        float2 bv = *(const float2*)(bias + c);
        *(uint32_t*)(dh + r * HIDN + c) =
            pack_h2(acc[mi][ni][0] + bv.x, acc[mi][ni][1] + bv.y);
        *(uint32_t*)(dh + (r + 8) * HIDN + c) =
            pack_h2(acc[mi][ni][2] + bv.x, acc[mi][ni][3] + bv.y);
      }
    }
  } else {                    // Q/K: fused RoPE (pair ni <-> ni+4 in-register)
    __half* dh = g_hi + (4L + mode) * MSZ;
    __half* dl = g_lo + (4L + mode) * MSZ;
#pragma unroll
    for (int mi = 0; mi < 4; mi++) {
      const long rb = row0 + wm * 64 + mi * 16 + (lane >> 2);
#pragma unroll
      for (int ni = 0; ni < 4; ni++) {
        const int c = col0 + wn * 64 + ni * 8 + (lane & 3) * 2;
        const int i0 = ni * 8 + (lane & 3) * 2;        // rope freq index (<31)
        float2 bA = *(const float2*)(bias + c);
        float2 bB = *(const float2*)(bias + c + 32);
#pragma unroll
        for (int half = 0; half < 2; half++) {
          const long r = rb + half * 8;
          const int sp = (int)(r & (SEQ - 1));
          float2 t0 = g_rope[sp * 32 + i0];
          float2 t1 = g_rope[sp * 32 + i0 + 1];
          float x1a = acc[mi][ni][half * 2]         + bA.x;
          float x1b = acc[mi][ni][half * 2 + 1]     + bA.y;
          float x2a = acc[mi][ni + 4][half * 2]     + bB.x;
          float x2b = acc[mi][ni + 4][half * 2 + 1] + bB.y;
          float o1a = x1a * t0.x - x2a * t0.y, o2a = x2a * t0.x + x1a * t0.y;
          float o1b = x1b * t1.x - x2b * t1.y, o2b = x2b * t1.x + x1b * t1.y;
          if (mode == 1) {
            uint32_t h, l;
            split2h(o1a, o1b, h, l);
            *(uint32_t*)(dh + r * HIDN + c) = h;
            *(uint32_t*)(dl + r * HIDN + c) = l;
            split2h(o2a, o2b, h, l);
            *(uint32_t*)(dh + r * HIDN + c + 32) = h;
            *(uint32_t*)(dl + r * HIDN + c + 32) = l;
          } else {
            *(uint32_t*)(dh + r * HIDN + c)      = pack_h2(o1a, o1b);
            *(uint32_t*)(dh + r * HIDN + c + 32) = pack_h2(o2a, o2b);
          }
        }
      }
    }
  }
}

// ---------------- fp16 tensor-core flash attention -------------------------
__device__ __forceinline__ void attn_load_kv(
    uint32_t sb, int st, const __half* Kh, const __half* Kl, const __half* Vh,
    const int* mask, char* smem, int b, int h, int k0, int t) {
#pragma unroll
  for (int j = 0; j < 4; j++) {
    const int idx = t + j * 128;
    const int r = idx >> 3, cc = idx & 7;
    const long off = (long)(b * SEQ + k0 + r) * HIDN + h * HDIM + cc * 8;
    const uint32_t so = sb + (uint32_t)(r * (ALD * 2) + cc * 16);
    cp16(so + SKH(st), Kh + off);
    cp16(so + SKL(st), Kl + off);
    cp16(so + SVH(st), Vh + off);
  }
  if (t < 64) ((int*)(smem + SMSK(st)))[t] = mask[b * SEQ + k0 + t];
}

__global__ __launch_bounds__(128, 3)
void attn_mma(const int* __restrict__ mask) {
  extern __shared__ __align__(128) char smem[];
  const uint32_t sb = (uint32_t)__cvta_generic_to_shared(smem);
  const int t = threadIdx.x, lane = t & 31, wid = t >> 5;
  const int b = blockIdx.z, h = blockIdx.y, q0 = blockIdx.x * 64;
  const int m0 = wid * 16;
  const __half* Qh = g_hi + 4L * MSZ;
  const __half* Kh = g_hi + 5L * MSZ;
  const __half* Kl = g_lo + 5L * MSZ;
  const __half* Vh = g_hi + 6L * MSZ;

#pragma unroll
  for (int j = 0; j < 4; j++) {
    const int idx = t + j * 128;
    const int r = idx >> 3, cc = idx & 7;
    const long off = (long)(b * SEQ + q0 + r) * HIDN + h * HDIM + cc * 8;
    cp16(sb + (uint32_t)(r * (ALD * 2) + cc * 16) + SQH, Qh + off);
  }
  attn_load_kv(sb, 0, Kh, Kl, Vh, mask, smem, b, h, 0, t);
  CP_COMMIT();
  CP_WAIT0();
  __syncthreads();

  uint32_t qh[4][4];
  {
    const uint32_t base =
        sb + (uint32_t)((m0 + (lane & 15)) * (ALD * 2) + (lane >> 4) * 16);
#pragma unroll
    for (int kc = 0; kc < 4; kc++) LDSM4(qh[kc], base + SQH + kc * 32);
  }

  float o[8][4];
#pragma unroll
  for (int i = 0; i < 8; i++)
#pragma unroll
    for (int j = 0; j < 4; j++) o[i][j] = 0.f;
  float mA = -1e30f, mB = -1e30f, lA = 0.f, lB = 0.f;

  for (int kb = 0; kb < SEQ / 64; kb++) {
    const int st = kb & 1;
    if (kb + 1 < SEQ / 64) {
      attn_load_kv(sb, st ^ 1, Kh, Kl, Vh, mask, smem, b, h, (kb + 1) * 64, t);
    }
    CP_COMMIT();
    CP_WAIT1();
    __syncthreads();

    float s[8][4];
#pragma unroll
    for (int i = 0; i < 8; i++)
#pragma unroll
      for (int j = 0; j < 4; j++) s[i][j] = 0.f;
#pragma unroll
    for (int kc = 0; kc < 4; kc++) {
      const uint32_t base =
          sb + (uint32_t)((lane & 15) * (ALD * 2) + (lane >> 4) * 16 + kc * 32);
#pragma unroll
      for (int np = 0; np < 4; np++) {
        uint32_t kh4[4], kl4[4];
        const uint32_t a = base + (uint32_t)(np * 16 * (ALD * 2));
        LDSM4(kh4, a + SKH(st));
        LDSM4(kl4, a + SKL(st));
        MMA(s[2 * np],     qh[kc], kh4[0], kh4[2]);
        MMA(s[2 * np],     qh[kc], kl4[0], kl4[2]);
        MMA(s[2 * np + 1], qh[kc], kh4[1], kh4[3]);
        MMA(s[2 * np + 1], qh[kc], kl4[1], kl4[3]);
      }
    }

    const int cbase = (lane & 3) * 2;
    const int* smk = (const int*)(smem + SMSK(st));
#pragma unroll
    for (int nt = 0; nt < 8; nt++) {
      const int c = nt * 8 + cbase;
      const int mk0 = smk[c], mk1 = smk[c + 1];
      s[nt][0] = mk0 ? s[nt][0] * 0.125f : 1e-10f;
      s[nt][2] = mk0 ? s[nt][2] * 0.125f : 1e-10f;
      s[nt][1] = mk1 ? s[nt][1] * 0.125f : 1e-10f;
      s[nt][3] = mk1 ? s[nt][3] * 0.125f : 1e-10f;
    }

    float bmA = -1e30f, bmB = -1e30f;
#pragma unroll
    for (int nt = 0; nt < 8; nt++) {
      bmA = fmaxf(bmA, fmaxf(s[nt][0], s[nt][1]));
      bmB = fmaxf(bmB, fmaxf(s[nt][2], s[nt][3]));
    }
#pragma unroll
    for (int off = 1; off <= 2; off <<= 1) {
      bmA = fmaxf(bmA, __shfl_xor_sync(0xffffffffu, bmA, off));
      bmB = fmaxf(bmB, __shfl_xor_sync(0xffffffffu, bmB, off));
    }
    const float mnA = fmaxf(mA, bmA), mnB = fmaxf(mB, bmB);
    const float cA = __expf(mA - mnA), cB = __expf(mB - mnB);
    mA = mnA; mB = mnB;
    float p[8][4];
    float sA = 0.f, sB = 0.f;
#pragma unroll
    for (int nt = 0; nt < 8; nt++) {
      p[nt][0] = __expf(s[nt][0] - mnA);
      p[nt][1] = __expf(s[nt][1] - mnA);
      p[nt][2] = __expf(s[nt][2] - mnB);
      p[nt][3] = __expf(s[nt][3] - mnB);
      sA += p[nt][0] + p[nt][1];
      sB += p[nt][2] + p[nt][3];
    }
#pragma unroll
    for (int off = 1; off <= 2; off <<= 1) {
      sA += __shfl_xor_sync(0xffffffffu, sA, off);
      sB += __shfl_xor_sync(0xffffffffu, sB, off);
    }
    lA = lA * cA + sA;
    lB = lB * cB + sB;
#pragma unroll
    for (int nt = 0; nt < 8; nt++) {
      o[nt][0] *= cA; o[nt][1] *= cA;
      o[nt][2] *= cB; o[nt][3] *= cB;
    }

    uint32_t ph[4][4], pl[4][4];
#pragma unroll
    for (int kc = 0; kc < 4; kc++) {
      split2h(p[2 * kc][0],     p[2 * kc][1],     ph[kc][0], pl[kc][0]);
      split2h(p[2 * kc][2],     p[2 * kc][3],     ph[kc][1], pl[kc][1]);
      split2h(p[2 * kc + 1][0], p[2 * kc + 1][1], ph[kc][2], pl[kc][2]);
      split2h(p[2 * kc + 1][2], p[2 * kc + 1][3], ph[kc][3], pl[kc][3]);
    }

#pragma unroll
    for (int kc = 0; kc < 4; kc++) {
      const uint32_t vbase =
          sb + (uint32_t)((kc * 16 + (lane & 15)) * (ALD * 2) + (lane >> 4) * 16);
#pragma unroll
      for (int np = 0; np < 4; np++) {
        uint32_t vh4[4];
        LDSM4T(vh4, vbase + (uint32_t)(np * 32) + SVH(st));
        MMA(o[2 * np],     ph[kc], vh4[0], vh4[1]);
        MMA(o[2 * np],     pl[kc], vh4[0], vh4[1]);
        MMA(o[2 * np + 1], ph[kc], vh4[2], vh4[3]);
        MMA(o[2 * np + 1], pl[kc], vh4[2], vh4[3]);
      }
    }
    __syncthreads();
  }

  const float iA = 1.f / lA, iB = 1.f / lB;
  const long rA = (long)(b * SEQ + q0 + m0 + (lane >> 2));
  const long rB = rA + 8;
#pragma unroll
  for (int nt = 0; nt < 8; nt++) {
    const int col = h * HDIM + nt * 8 + (lane & 3) * 2;
    *(float2*)(g_X + rA * HIDN + col) = make_float2(o[nt][0] * iA, o[nt][1] * iA);
    *(float2*)(g_X + rB * HIDN + col) = make_float2(o[nt][2] * iB, o[nt][3] * iB);
  }
}

// ---------------- launch -----------------------------------------------------
extern "C" void kernel_launch(void* const* d_in, const int* in_sizes, int n_in,
                              void* d_out, int out_size) {
  const float* q   = (const float*)d_in[0];
  const float* k   = (const float*)d_in[1];
  const float* v   = (const float*)d_in[2];
  const float* g1q = (const float*)d_in[3];
  const float* b1q = (const float*)d_in[4];
  const float* g1k = (const float*)d_in[5];
  const float* b1k = (const float*)d_in[6];
  const float* g1v = (const float*)d_in[7];
  const float* b1v = (const float*)d_in[8];
  const float* Wq  = (const float*)d_in[9];
  const float* bq  = (const float*)d_in[10];
  const float* Wk  = (const float*)d_in[11];
  const float* bk  = (const float*)d_in[12];
  const float* Wv  = (const float*)d_in[13];
  const float* bv  = (const float*)d_in[14];
  const float* g2  = (const float*)d_in[15];
  const float* b2  = (const float*)d_in[16];
  const float* g3  = (const float*)d_in[17];
  const float* b3  = (const float*)d_in[18];
  const float* Wf  = (const float*)d_in[19];
  const float* bf  = (const float*)d_in[20];
  const int*  mask = (const int*)d_in[21];
  float* out = (float*)d_out;

  cudaFuncSetAttribute(gemm_mma, cudaFuncAttributeMaxDynamicSharedMemorySize, GEMM_SMEM);
  cudaFuncSetAttribute(attn_mma, cudaFuncAttributeMaxDynamicSharedMemorySize, ATTN_SMEM);

  // 0) rope table + weight split
  rope_table_kernel<<<64, 512>>>();
  wconv_kernel<<<dim3(WSZ / 1024, 4), 256>>>(Wq, Wk, Wv, Wf);

  // 1) LayerNorms of q,k,v -> fp16 hi slots 0..2
  ln3_kernel<<<dim3(MROWS, 3), 256>>>(q, g1q, b1q, k, g1k, b1k, v, g1v, b1v);

  // 2) Q/K/V projections + fused bias/RoPE/split -> slots 4,5,6
  gemm_mma<<<dim3(HIDN / BN, MROWS / BM, 3), 256, GEMM_SMEM>>>(0, bq, bk, bv);

  // 3) fp16 tensor-core flash attention -> g_X
  attn_mma<<<dim3(SEQ / 64, NHEAD, 4), 128, ATTN_SMEM>>>(mask);

  // 4) fx = LN(x) -> g_Fx fp32 + slot 3 fp16 hi
  ln_fx_kernel<<<MROWS, 256>>>(g2, b2);

  // 5) fo = relu(fx @ Wf^T + bf) -> g_Fo fp32
  gemm_mma<<<dim3(HIDN / BN, MROWS / BM, 1), 256, GEMM_SMEM>>>(1, bf, bf, bf);

  // 6) out = fx + LN(fo)
  ln_add_kernel<<<MROWS, 256>>>(g3, b3, out);
}